// round 1
// baseline (speedup 1.0000x reference)
#include <cuda_runtime.h>

// Problem constants (from reference): B=16, C=64, H=W=256, STRIDE=2, KS=3
#define BCN   1024          // B*C
#define HH    256
#define WW    256
#define HP    128
#define WP    128
#define TH    16            // output rows per block (full-width stripe)
#define CAN_H (TH + 2)      // 18 canvas rows
#define CAN_WU 258          // used canvas cols
#define CAN_W  260          // padded to multiple of 4 for float4 alignment
#define PT_H  (TH / 2 + 2)  // 10 pooled rows staged

__device__ __forceinline__ float neg_inf() { return __int_as_float(0xff800000); }

__global__ __launch_bounds__(256, 2)
void morph_unpool_dilate_kernel(const float* __restrict__ f,
                                const int*   __restrict__ prov,
                                float*       __restrict__ out)
{
    __shared__ float canvas[CAN_H][CAN_W];
    __shared__ int   sprov[PT_H][WP];
    __shared__ float sval [PT_H][WP];

    const int bid  = blockIdx.x;
    const int bc   = bid >> 4;        // which (b,c) plane
    const int tile = bid & 15;        // which 16-row stripe
    const int R0   = tile * TH;       // first output row of stripe (even)
    const int I0   = tile * (TH / 2); // first "main" pooled row
    const int tid  = threadIdx.x;

    const float* fb = f    + (size_t)bc * (HP * WP);
    const int*   pb = prov + (size_t)bc * (HP * WP);

    // ---- Stage pooled tile: rows I0-1 .. I0+8, all 128 cols (coalesced) ----
    for (int idx = tid; idx < PT_H * WP; idx += 256) {
        int li = idx >> 7;        // local pooled row 0..9
        int j  = idx & 127;
        int i  = I0 - 1 + li;
        if ((unsigned)i < HP) {
            sprov[li][j] = pb[i * WP + j];
            sval [li][j] = fb[i * WP + j];
        } else {
            sprov[li][j] = -1;    // never matches a valid target
        }
    }
    __syncthreads();

    // ---- Build canvas (unpooled image + 1-pixel halo), priority gather ----
    // Canvas rows cover image rows R0-1 .. R0+16, cols -1 .. 256.
    // Candidate source cells for image pixel (cr,cc):
    //   i in { cr>>1, cr>>1 - 1 (only if cr even) }, same for j with cc.
    // XLA sequential scatter => last-write-wins in pooled row-major order,
    // i.e. the candidate with the LARGEST i*WP+j wins. Check in descending
    // priority: (ih,jh) > (ih,jl) > (il,jh) > (il,jl).
    for (int idx = tid; idx < CAN_H * CAN_WU; idx += 256) {
        int lr = idx / CAN_WU;
        int lc = idx - lr * CAN_WU;
        int cr = R0 - 1 + lr;
        int cc = lc - 1;
        float v;
        if ((unsigned)cr >= HH || (unsigned)cc >= WW) {
            v = neg_inf();                    // reduce_window -inf padding
        } else {
            const int target = (cr << 8) | cc; // cr*W + cc
            const int ih  = cr >> 1;
            const int jh  = cc >> 1;
            const int lih = ih - I0 + 1;       // local row of ih (1..? always in [0,9])
            const bool hasIlo = ((cr & 1) == 0) && (ih > 0);
            const bool hasJlo = ((cc & 1) == 0) && (jh > 0);
            v = 0.0f;                          // empty canvas value
            if (sprov[lih][jh] == target)                      v = sval[lih][jh];
            else if (hasJlo && sprov[lih][jh - 1] == target)   v = sval[lih][jh - 1];
            else if (hasIlo && sprov[lih - 1][jh] == target)   v = sval[lih - 1][jh];
            else if (hasIlo && hasJlo &&
                     sprov[lih - 1][jh - 1] == target)         v = sval[lih - 1][jh - 1];
        }
        canvas[lr][lc] = v;
    }
    __syncthreads();

    // ---- 3x3 max dilation + coalesced float4 stores ----
    // Thread t handles column group g = t&63 (cols 4g..4g+3) on rows
    // (t>>6) + 4k, k = 0..3.  Canvas cols needed: 4g .. 4g+5 -> two aligned
    // float4 loads per canvas row (LDS.128, conflict-free).
    float* ob = out + (size_t)bc * (HH * WW) + (size_t)R0 * WW;
    const int g   = tid & 63;
    const int rb  = tid >> 6;
    const int cb  = g << 2;           // output col base (=canvas col base of A)

    #pragma unroll
    for (int k = 0; k < 4; k++) {
        const int lo = rb + (k << 2);     // local output row 0..15
        float c0 = neg_inf(), c1 = c0, c2 = c0, c3 = c0, c4 = c0, c5 = c0;
        #pragma unroll
        for (int dr = 0; dr < 3; dr++) {
            const float4 a = *reinterpret_cast<const float4*>(&canvas[lo + dr][cb]);
            const float4 b = *reinterpret_cast<const float4*>(&canvas[lo + dr][cb + 4]);
            c0 = fmaxf(c0, a.x); c1 = fmaxf(c1, a.y);
            c2 = fmaxf(c2, a.z); c3 = fmaxf(c3, a.w);
            c4 = fmaxf(c4, b.x); c5 = fmaxf(c5, b.y);
        }
        float4 o;
        o.x = fmaxf(fmaxf(c0, c1), c2);
        o.y = fmaxf(fmaxf(c1, c2), c3);
        o.z = fmaxf(fmaxf(c2, c3), c4);
        o.w = fmaxf(fmaxf(c3, c4), c5);
        *reinterpret_cast<float4*>(&ob[lo * WW + cb]) = o;
    }
}

extern "C" void kernel_launch(void* const* d_in, const int* in_sizes, int n_in,
                              void* d_out, int out_size)
{
    const float* f    = (const float*)d_in[0];
    const int*   prov = (const int*)  d_in[1];
    // d_in[2], d_in[3] are scalar h, w (256, 256) — hardcoded above.
    float* out = (float*)d_out;
    morph_unpool_dilate_kernel<<<BCN * 16, 256>>>(f, prov, out);
}

// round 2
// speedup vs baseline: 2.3483x; 2.3483x over previous
#include <cuda_runtime.h>

// B=16, C=64, H=W=256, STRIDE=2, IN_KS=OUT_KS=3
#define HH 256
#define WW 256
#define HP 128
#define WP 128
#define TH 16              // output rows per block
#define CAN_H 18           // canvas rows: image rows R0-1 .. R0+16
#define CAN_W 260          // padded row (258 used) for float4 alignment
#define CAN_WU 258
#define PR_H 11            // staged prov rows I0-1 .. I0+8, + sentinel row
#define PR_W 132           // col halo: j = -1 .. 129 (+pad)

__global__ __launch_bounds__(256, 4)
void morph_unpool_dilate_kernel(const float* __restrict__ f,
                                const int*   __restrict__ prov,
                                float*       __restrict__ out)
{
    __shared__ float canvas[CAN_H][CAN_W];
    __shared__ int   sprov[PR_H][PR_W];

    const int   bid  = blockIdx.x;
    const int   bc   = bid >> 4;
    const int   tile = bid & 15;
    const int   R0   = tile * TH;
    const int   I0   = tile * (TH / 2);
    const int   tid  = threadIdx.x;
    const float NEG  = __int_as_float(0xff800000);

    const float* fb = f    + (size_t)bc * (HP * WP);
    const int*   pb = prov + (size_t)bc * (HP * WP);

    // ---- Phase 1: zero-fill canvas (float4) + stage provenance with halo ----
    {
        float4* c4 = (float4*)&canvas[0][0];
        for (int i = tid; i < (CAN_H * CAN_W) / 4; i += 256)
            c4[i] = make_float4(0.f, 0.f, 0.f, 0.f);
    }
    for (int idx = tid; idx < PR_H * PR_W; idx += 256) {
        int li = idx / PR_W;         // 0..10  (cell row i = I0-1+li; row 10 = sentinel)
        int jj = idx - li * PR_W;    // 0..131 (cell col j = jj-1)
        int i  = I0 - 1 + li;
        int j  = jj - 1;
        int v  = -2;                 // sentinel: never equals a valid target
        if (li < 10 && (unsigned)i < HP && (unsigned)j < WP)
            v = pb[i * WP + j];
        sprov[li][jj] = v;
    }
    __syncthreads();

    // ---- Phase 2a: -inf borders (out-of-image halo; never scatter targets) ----
    if (tid < CAN_H * 2) {
        int r = tid >> 1;
        canvas[r][(tid & 1) ? (WW + 1) : 0] = NEG;
    }
    if (tile == 0)
        for (int c = tid; c < CAN_WU; c += 256) canvas[0][c] = NEG;
    if (tile == 15)
        for (int c = tid; c < CAN_WU; c += 256) canvas[CAN_H - 1][c] = NEG;

    // ---- Phase 2b: race-free deterministic scatter ----
    // Collisions only between cells with |di|<=1,|dj|<=1; winner = largest
    // linear index (XLA sequential scatter, last write wins). A cell writes
    // iff none of its 4 higher-priority neighbors targets the same pixel.
    #pragma unroll
    for (int it = 0; it < 5; it++) {
        int idx = it * 256 + tid;        // 0..1279
        int li  = idx >> 7;              // 0..9
        int j   = idx & 127;
        int i   = I0 - 1 + li;
        if ((unsigned)i < HP) {
            int  t   = sprov[li][j + 1];         // own target (r*256+c)
            int  n1  = sprov[li][j + 2];         // (i,   j+1)
            int  n2  = sprov[li + 1][j];         // (i+1, j-1)
            int  n3  = sprov[li + 1][j + 1];     // (i+1, j  )
            int  n4  = sprov[li + 1][j + 2];     // (i+1, j+1)
            bool sup = (n1 == t) | (n2 == t) | (n3 == t) | (n4 == t);
            int  r   = t >> 8;
            int  c   = t & 255;
            int  lr  = r - R0 + 1;
            if (!sup && (unsigned)lr < CAN_H)
                canvas[lr][c + 1] = fb[i * WP + j];
        }
    }
    __syncthreads();

    // ---- Phase 3: separable 3x3 max with vertical register reuse ----
    // Thread: col group cb..cb+3, four consecutive output rows base..base+3.
    // 6 canvas-row loads (float4 + float2) -> horizontal max -> rolling
    // vertical max -> 4 coalesced float4 stores. 3 LDS.128 per output vs 6.
    const int cb   = (tid & 63) << 2;
    const int base = (tid >> 6) << 2;
    float* ob = out + (size_t)bc * (HH * WW) + (size_t)R0 * WW + cb;

    auto hrow = [&](int cr) -> float4 {
        float4 a = *(const float4*)&canvas[cr][cb];
        float2 b = *(const float2*)&canvas[cr][cb + 4];
        float  m = fmaxf(a.y, a.z);
        float  n = fmaxf(a.w, b.x);
        float4 h;
        h.x = fmaxf(m, a.x);
        h.y = fmaxf(m, a.w);
        h.z = fmaxf(a.z, n);
        h.w = fmaxf(n, b.y);
        return h;
    };

    float4 h0 = hrow(base);
    float4 h1 = hrow(base + 1);
    #pragma unroll
    for (int k = 0; k < 4; k++) {
        float4 h2 = hrow(base + k + 2);
        float4 o;
        o.x = fmaxf(fmaxf(h0.x, h1.x), h2.x);
        o.y = fmaxf(fmaxf(h0.y, h1.y), h2.y);
        o.z = fmaxf(fmaxf(h0.z, h1.z), h2.z);
        o.w = fmaxf(fmaxf(h0.w, h1.w), h2.w);
        *(float4*)&ob[(base + k) * WW] = o;
        h0 = h1; h1 = h2;
    }
}

extern "C" void kernel_launch(void* const* d_in, const int* in_sizes, int n_in,
                              void* d_out, int out_size)
{
    const float* f    = (const float*)d_in[0];
    const int*   prov = (const int*)  d_in[1];
    float* out = (float*)d_out;
    morph_unpool_dilate_kernel<<<16384, 256>>>(f, prov, out);
}

// round 3
// speedup vs baseline: 4.2634x; 1.8155x over previous
#include <cuda_runtime.h>

// B=16, C=64, H=W=256, STRIDE=2, IN_KS=OUT_KS=3
#define HH 256
#define WW 256
#define HP 128
#define WP 128
#define TH 32              // output rows per block
#define NT 8               // tiles per plane (256/32)
#define CAN_H 34           // canvas rows: image rows R0-1 .. R0+32
#define CAN_W 260          // 258 used, padded for float4
#define PR_H 19            // staged prov rows I0-1 .. I0+17
#define PR_W 136           // ushort cols; cell j at index j+4, halos at 3 and 132

__global__ __launch_bounds__(256, 5)
void morph_unpool_dilate_kernel(const float* __restrict__ f,
                                const int*   __restrict__ prov,
                                float*       __restrict__ out)
{
    __shared__ float          canvas[CAN_H][CAN_W];
    __shared__ unsigned short sprov[PR_H][PR_W];

    const int   bid  = blockIdx.x;
    const int   bc   = bid >> 3;          // plane (b*c)
    const int   tile = bid & 7;
    const int   R0   = tile * TH;
    const int   I0   = tile * (TH / 2);
    const int   tid  = threadIdx.x;
    const float NEG  = __int_as_float(0xff800000);

    const float4* fb4 = (const float4*)(f + (size_t)bc * (HP * WP));
    const int4*   pb4 = (const int4*)  (prov + (size_t)bc * (HP * WP));

    // ---- Phase 1a: zero-fill canvas with fused -inf borders ----
    for (int idx = tid; idx < CAN_H * (CAN_W / 4); idx += 256) {
        int row = idx / 65;
        int cg  = idx - row * 65;
        float4 v = make_float4(0.f, 0.f, 0.f, 0.f);
        if (cg == 0)  v.x = NEG;              // image col -1 (canvas col 0)
        if (cg == 64) v.y = NEG;              // image col 256 (canvas col 257)
        if ((tile == 0 && row == 0) || (tile == NT - 1 && row == CAN_H - 1))
            v = make_float4(NEG, NEG, NEG, NEG);
        ((float4*)&canvas[0][0])[row * 65 + cg] = v;
    }

    // ---- Phase 1b: stage provenance as u16 (int4 loads, ushort4 stores) ----
    for (int idx = tid; idx < PR_H * 32; idx += 256) {
        int li = idx >> 5;                    // 0..18 -> cell row i = I0-1+li
        int g  = idx & 31;
        int i  = I0 - 1 + li;
        ushort4 s;
        if ((unsigned)i < HP) {
            int4 p = pb4[i * 32 + g];
            s = make_ushort4((unsigned short)p.x, (unsigned short)p.y,
                             (unsigned short)p.z, (unsigned short)p.w);
        } else {
            // bottom sentinel 0: comparers (row 127 / row I0+16) have t>=8192
            // top rows are never read as below-neighbors
            s = make_ushort4(0, 0, 0, 0);
        }
        *(ushort4*)&sprov[li][(g << 2) + 4] = s;
    }
    if (tid < PR_H * 2) {                     // column halos
        int li = tid >> 1;
        if (tid & 1) sprov[li][132] = 0;      // j=128: comparers have c>=254
        else         sprov[li][3]   = 0xFFFF; // j=-1 : comparers have c<=2
    }
    __syncthreads();

    // ---- Phase 2: race-free deterministic scatter (last-write-wins) ----
    // Cell (i,j) writes iff none of (i,j+1),(i+1,j-1),(i+1,j),(i+1,j+1)
    // targets the same pixel (those have larger linear index = higher priority).
    for (int idx = tid; idx < 18 * 32; idx += 256) {
        int li = idx >> 5;
        int g  = idx & 31;
        int i  = I0 - 1 + li;
        if ((unsigned)i < HP) {
            int j = g << 2;
            ushort4 o  = *(const ushort4*)&sprov[li][j + 4];
            ushort4 bw = *(const ushort4*)&sprov[li + 1][j + 4];
            int rr = sprov[li][j + 8];
            int bl = sprov[li + 1][j + 3];
            int br = sprov[li + 1][j + 8];
            float4 fv = fb4[i * 32 + g];
            int t0 = o.x,  t1 = o.y,  t2 = o.z,  t3 = o.w;
            int b0 = bw.x, b1 = bw.y, b2 = bw.z, b3 = bw.w;

            #define SCATTER(t, n1, n2, n3, n4, val)                          \
            {                                                                \
                bool sup = ((n1) == (t)) | ((n2) == (t)) |                   \
                           ((n3) == (t)) | ((n4) == (t));                    \
                int lr = ((t) >> 8) - R0 + 1;                                \
                if (!sup && (unsigned)lr < CAN_H)                            \
                    canvas[lr][((t) & 255) + 1] = (val);                     \
            }
            SCATTER(t0, t1, bl, b0, b1, fv.x);
            SCATTER(t1, t2, b0, b1, b2, fv.y);
            SCATTER(t2, t3, b1, b2, b3, fv.z);
            SCATTER(t3, rr, b2, b3, br, fv.w);
            #undef SCATTER
        }
    }
    __syncthreads();

    // ---- Phase 3: separable 3x3 max, 8-row strips, rolling vertical max ----
    // Thread: col group cb..cb+3, strip of 8 output rows; 10 canvas row loads.
    const int g    = tid & 63;
    const int cb   = g << 2;
    const int s    = tid >> 6;            // strip 0..3
    const int base = s << 3;              // local output row base
    float* ob = out + (size_t)bc * (HH * WW) + (size_t)(R0 + base) * WW + cb;

    auto hrow = [&](int cr) -> float4 {
        float4 a = *(const float4*)&canvas[cr][cb];
        float2 b = *(const float2*)&canvas[cr][cb + 4];
        float  m = fmaxf(a.y, a.z);
        float  n = fmaxf(a.w, b.x);
        float4 h;
        h.x = fmaxf(m, a.x);
        h.y = fmaxf(m, a.w);
        h.z = fmaxf(a.z, n);
        h.w = fmaxf(n, b.y);
        return h;
    };

    float4 h0 = hrow(base);
    float4 h1 = hrow(base + 1);
    #pragma unroll
    for (int k = 0; k < 8; k++) {
        float4 h2 = hrow(base + k + 2);
        float4 o;
        o.x = fmaxf(fmaxf(h0.x, h1.x), h2.x);
        o.y = fmaxf(fmaxf(h0.y, h1.y), h2.y);
        o.z = fmaxf(fmaxf(h0.z, h1.z), h2.z);
        o.w = fmaxf(fmaxf(h0.w, h1.w), h2.w);
        *(float4*)&ob[k * WW] = o;
        h0 = h1; h1 = h2;
    }
}

extern "C" void kernel_launch(void* const* d_in, const int* in_sizes, int n_in,
                              void* d_out, int out_size)
{
    const float* f    = (const float*)d_in[0];
    const int*   prov = (const int*)  d_in[1];
    float* out = (float*)d_out;
    morph_unpool_dilate_kernel<<<1024 * NT, 256>>>(f, prov, out);
}